// round 2
// baseline (speedup 1.0000x reference)
#include <cuda_runtime.h>

// WindowedSelfAttention3D — fused, one CTA per 4x4x4 window.
// R2: GEMM remapped (rm=2, rn=8) for conflict-free broadcast-heavy smem loads.

#define CCH   128
#define TOK   64
#define RS    132    // row stride (floats); RS/4=33 odd -> 8 consecutive rows conflict-free
#define SCS   68     // scores row stride (17 16B-units, odd)
#define VOLS  262144 // 64*64*64

typedef unsigned long long u64t;

__device__ __forceinline__ u64t pk2(float lo, float hi) {
    u64t r; asm("mov.b64 %0, {%1, %2};" : "=l"(r) : "f"(lo), "f"(hi)); return r;
}
__device__ __forceinline__ void fma2(u64t& d, u64t a, u64t b) {
    asm("fma.rn.f32x2 %0, %1, %2, %0;" : "+l"(d) : "l"(a), "l"(b));
}
__device__ __forceinline__ float red2(u64t v) {
    float lo, hi; asm("mov.b64 {%0, %1}, %2;" : "=f"(lo), "=f"(hi) : "l"(v));
    return lo + hi;
}
__device__ __forceinline__ void unpk(u64t v, float& lo, float& hi) {
    asm("mov.b64 {%0, %1}, %2;" : "=f"(lo), "=f"(hi) : "l"(v));
}

// C[64x64] += A[64xKK] * B[64xKK]^T ; thread: rows {tg*2,tg*2+1}, cols ng*8..ng*8+7
template<int KK>
__device__ __forceinline__ void gemm28(const float* __restrict__ A,
                                       const float* __restrict__ B,
                                       int tg, int ng, float out[2][8]) {
    u64t acc[2][8];
#pragma unroll
    for (int i = 0; i < 2; i++)
#pragma unroll
        for (int j = 0; j < 8; j++) acc[i][j] = 0ull;

    const float* a0p = A + (tg * 2) * RS;
    const float* a1p = a0p + RS;
    const float* bp  = B + (ng * 8) * RS;

#pragma unroll 4
    for (int k = 0; k < KK; k += 4) {
        ulonglong2 a0 = *(const ulonglong2*)(a0p + k);
        ulonglong2 a1 = *(const ulonglong2*)(a1p + k);
        ulonglong2 b[8];
#pragma unroll
        for (int j = 0; j < 8; j++)
            b[j] = *(const ulonglong2*)(bp + j * RS + k);
#pragma unroll
        for (int j = 0; j < 8; j++) {
            fma2(acc[0][j], a0.x, b[j].x);
            fma2(acc[0][j], a0.y, b[j].y);
            fma2(acc[1][j], a1.x, b[j].x);
            fma2(acc[1][j], a1.y, b[j].y);
        }
    }
#pragma unroll
    for (int i = 0; i < 2; i++)
#pragma unroll
        for (int j = 0; j < 8; j++) out[i][j] = red2(acc[i][j]);
}

__global__ __launch_bounds__(256, 1)
void win_attn_kernel(const float* __restrict__ x,
                     const float* __restrict__ ln_g, const float* __restrict__ ln_b,
                     const float* __restrict__ Win,  const float* __restrict__ bin,
                     const float* __restrict__ Wout, const float* __restrict__ bout,
                     const float* __restrict__ Wc,   const float* __restrict__ bc,
                     float* __restrict__ out) {
    extern __shared__ float sm[];
    float* XW = sm;              // [64][132] original window (residual)
    float* XN = XW + TOK * RS;   // [64][132] LN output, later attn o
    float* Qb = XN + TOK * RS;   // [64][132] q, later y = xw + attn_out
    float* Kb = Qb + TOK * RS;   // [64][132]
    float* Vb = Kb + TOK * RS;   // [64][132]
    float* WT = Vb + TOK * RS;   // [64][132] weight tile
    float* SC = WT + TOK * RS;   // [64][68]  scores (per head)

    const int tid = threadIdx.x;
    const int wid = blockIdx.x;
    const int bb  = wid >> 12;
    const int rr  = wid & 4095;
    const int vd0 = (rr >> 8) * 4;
    const int vh0 = ((rr >> 4) & 15) * 4;
    const int vw0 = (rr & 15) * 4;
    const float* xb = x + (size_t)bb * ((size_t)CCH * VOLS);
    const size_t vox0 = (size_t)vd0 * 4096 + (size_t)vh0 * 64 + vw0;

    // ---- gather window into XW ----
    for (int e = tid; e < TOK * CCH / 4; e += 256) {
        int c = e >> 4, tq = e & 15;
        int dz = tq >> 2, dy = tq & 3;
        float4 v = *(const float4*)(xb + (size_t)c * VOLS + vox0 + dz * 4096 + dy * 64);
        float* dst = XW + (dz * 16 + dy * 4) * RS + c;
        dst[0] = v.x; dst[RS] = v.y; dst[2 * RS] = v.z; dst[3 * RS] = v.w;
    }
    __syncthreads();

    // ---- LayerNorm over C=128 (4 threads per token) ----
    {
        int t = tid >> 2, sub = tid & 3;
        const float* row = XW + t * RS;
        float s = 0.f, ss = 0.f;
#pragma unroll 8
        for (int c = sub * 32; c < sub * 32 + 32; c++) { float v = row[c]; s += v; ss += v * v; }
        s  += __shfl_xor_sync(0xffffffffu, s, 1);  s  += __shfl_xor_sync(0xffffffffu, s, 2);
        ss += __shfl_xor_sync(0xffffffffu, ss, 1); ss += __shfl_xor_sync(0xffffffffu, ss, 2);
        float mu = s * (1.f / 128.f);
        float var = ss * (1.f / 128.f) - mu * mu;
        float rstd = rsqrtf(var + 1e-5f);
        float* nrow = XN + t * RS;
#pragma unroll 8
        for (int c = sub * 32; c < sub * 32 + 32; c++)
            nrow[c] = (row[c] - mu) * rstd * ln_g[c] + ln_b[c];
    }
    __syncthreads();

    const int tg = tid >> 3, ng = tid & 7;   // rows {tg*2, tg*2+1}, cols ng*8..+7

    // ---- QKV projection ----
    for (int nt = 0; nt < 6; nt++) {
        __syncthreads();
        for (int e = tid; e < 64 * 32; e += 256) {
            int o = e >> 5, k4 = e & 31;
            float4 w = *((const float4*)(Win + (size_t)(nt * 64 + o) * 128) + k4);
            *(float4*)(WT + o * RS + k4 * 4) = w;
        }
        __syncthreads();
        float accf[2][8];
        gemm28<128>(XN, WT, tg, ng, accf);
        float* dst = (nt < 2) ? Qb : (nt < 4) ? Kb : Vb;
        int cb = (nt & 1) * 64;
#pragma unroll
        for (int j = 0; j < 8; j++) {
            int cl = cb + ng * 8 + j;
            float bias = bin[nt * 64 + ng * 8 + j];
            dst[(tg * 2 + 0) * RS + cl] = accf[0][j] + bias;
            dst[(tg * 2 + 1) * RS + cl] = accf[1][j] + bias;
        }
    }

    // ---- attention per head (hd=32), o written into XN ----
    const float sc_norm = 0.17677669529663687f; // 1/sqrt(32)
    for (int hh = 0; hh < 4; hh++) {
        __syncthreads();
        // scores = q_h @ k_h^T * sc_norm
        {
            float accf[2][8];
            gemm28<32>(Qb + hh * 32, Kb + hh * 32, tg, ng, accf);
#pragma unroll
            for (int i = 0; i < 2; i++)
#pragma unroll
                for (int j = 0; j < 8; j++)
                    SC[(tg * 2 + i) * SCS + ng * 8 + j] = accf[i][j] * sc_norm;
        }
        __syncthreads();
        // softmax over keys, 4 threads per row
        {
            int rrow = tid >> 2, sub = tid & 3;
            float* row = SC + rrow * SCS + sub * 16;
            float m = row[0];
#pragma unroll
            for (int c = 1; c < 16; c++) m = fmaxf(m, row[c]);
            m = fmaxf(m, __shfl_xor_sync(0xffffffffu, m, 1));
            m = fmaxf(m, __shfl_xor_sync(0xffffffffu, m, 2));
            float s = 0.f;
#pragma unroll
            for (int c = 0; c < 16; c++) { float e = __expf(row[c] - m); row[c] = e; s += e; }
            s += __shfl_xor_sync(0xffffffffu, s, 1);
            s += __shfl_xor_sync(0xffffffffu, s, 2);
            float inv = 1.f / s;
#pragma unroll
            for (int c = 0; c < 16; c++) row[c] *= inv;
        }
        __syncthreads();
        // o_h = attn @ v_h : thread rows {tg*2,tg*2+1}, cols hh*32 + ng*4..+3
        {
            u64t acc[2][2] = {{0ull, 0ull}, {0ull, 0ull}};
            const float* s0 = SC + (tg * 2) * SCS;
            const float* s1 = s0 + SCS;
            const float* vp = Vb + hh * 32 + ng * 4;
#pragma unroll 8
            for (int k = 0; k < 64; k++) {
                float a0 = s0[k], a1 = s1[k];
                ulonglong2 bv = *(const ulonglong2*)(vp + k * RS);
                u64t ap0 = pk2(a0, a0), ap1 = pk2(a1, a1);
                fma2(acc[0][0], ap0, bv.x); fma2(acc[0][1], ap0, bv.y);
                fma2(acc[1][0], ap1, bv.x); fma2(acc[1][1], ap1, bv.y);
            }
#pragma unroll
            for (int i = 0; i < 2; i++) {
                float* dst = XN + (tg * 2 + i) * RS + hh * 32 + ng * 4;
                float lo, hi;
                unpk(acc[i][0], lo, hi); dst[0] = lo; dst[1] = hi;
                unpk(acc[i][1], lo, hi); dst[2] = lo; dst[3] = hi;
            }
        }
    }

    // ---- out_proj: y = xw + o @ Wout^T + bout  (into Qb) ----
    for (int nt = 0; nt < 2; nt++) {
        __syncthreads();
        for (int e = tid; e < 64 * 32; e += 256) {
            int o = e >> 5, k4 = e & 31;
            float4 w = *((const float4*)(Wout + (size_t)(nt * 64 + o) * 128) + k4);
            *(float4*)(WT + o * RS + k4 * 4) = w;
        }
        __syncthreads();
        float accf[2][8];
        gemm28<128>(XN, WT, tg, ng, accf);
#pragma unroll
        for (int j = 0; j < 8; j++) {
            int cc = nt * 64 + ng * 8 + j;
            float bias = bout[cc];
#pragma unroll
            for (int i = 0; i < 2; i++) {
                int t = tg * 2 + i;
                Qb[t * RS + cc] = XW[t * RS + cc] + accf[i][j] + bias;
            }
        }
    }

    // ---- 1x1x1 conv + residual, scatter to global ----
    float* outp = out + (size_t)bb * ((size_t)CCH * VOLS);
    const int t0 = tg * 2;
    const int dz = t0 >> 4, dy = (t0 >> 2) & 3, dx = t0 & 3;
    for (int nt = 0; nt < 2; nt++) {
        __syncthreads();
        for (int e = tid; e < 64 * 32; e += 256) {
            int o = e >> 5, k4 = e & 31;
            float4 w = *((const float4*)(Wc + (size_t)(nt * 64 + o) * 128) + k4);
            *(float4*)(WT + o * RS + k4 * 4) = w;
        }
        __syncthreads();
        float accf[2][8];
        gemm28<128>(Qb, WT, tg, ng, accf);
#pragma unroll
        for (int j = 0; j < 8; j++) {
            int cc = nt * 64 + ng * 8 + j;
            float bias = bc[cc];
            float2 o2;
            o2.x = accf[0][j] + bias + XW[(t0 + 0) * RS + cc];
            o2.y = accf[1][j] + bias + XW[(t0 + 1) * RS + cc];
            *(float2*)(outp + (size_t)cc * VOLS + vox0 + dz * 4096 + dy * 64 + dx) = o2;
        }
    }
}

static const int SMEM_BYTES = (6 * TOK * RS + TOK * SCS) * 4; // 220160 B

extern "C" void kernel_launch(void* const* d_in, const int* in_sizes, int n_in,
                              void* d_out, int out_size) {
    const float* x    = (const float*)d_in[0];
    const float* ln_g = (const float*)d_in[1];
    const float* ln_b = (const float*)d_in[2];
    const float* Win  = (const float*)d_in[3];
    const float* bin  = (const float*)d_in[4];
    const float* Wout = (const float*)d_in[5];
    const float* bout = (const float*)d_in[6];
    const float* Wc   = (const float*)d_in[7];
    const float* bc   = (const float*)d_in[8];
    float* out = (float*)d_out;

    cudaFuncSetAttribute(win_attn_kernel,
                         cudaFuncAttributeMaxDynamicSharedMemorySize, SMEM_BYTES);
    win_attn_kernel<<<8192, 256, SMEM_BYTES>>>(x, ln_g, ln_b, Win, bin,
                                               Wout, bout, Wc, bc, out);
}

// round 3
// speedup vs baseline: 4.9286x; 4.9286x over previous
#include <cuda_runtime.h>

// WindowedSelfAttention3D — fused, one CTA per 4x4x4 window.
// R3: (rm=2, rn=8) GEMM with INTERLEAVED column ownership (col = ng + 8j):
// at inner step j the 8 lanes hit 8 distinct 16B bank-phases -> conflict-free.

#define CCH   128
#define TOK   64
#define RS    132    // row stride (floats); 33 16B-units (odd) -> phase(r) = r mod 8
#define SCS   68     // scores row stride
#define VOLS  262144 // 64*64*64

typedef unsigned long long u64t;

__device__ __forceinline__ u64t pk2(float lo, float hi) {
    u64t r; asm("mov.b64 %0, {%1, %2};" : "=l"(r) : "f"(lo), "f"(hi)); return r;
}
__device__ __forceinline__ void fma2(u64t& d, u64t a, u64t b) {
    asm("fma.rn.f32x2 %0, %1, %2, %0;" : "+l"(d) : "l"(a), "l"(b));
}
__device__ __forceinline__ float red2(u64t v) {
    float lo, hi; asm("mov.b64 {%0, %1}, %2;" : "=f"(lo), "=f"(hi) : "l"(v));
    return lo + hi;
}
__device__ __forceinline__ void unpk(u64t v, float& lo, float& hi) {
    asm("mov.b64 {%0, %1}, %2;" : "=f"(lo), "=f"(hi) : "l"(v));
}

// C[64x64] = A[64xKK] * B[64xKK]^T
// thread: rows {tg*2, tg*2+1}, cols {ng + 8j, j=0..7}  (interleaved!)
template<int KK>
__device__ __forceinline__ void gemm28(const float* __restrict__ A,
                                       const float* __restrict__ B,
                                       int tg, int ng, float out[2][8]) {
    u64t acc[2][8];
#pragma unroll
    for (int i = 0; i < 2; i++)
#pragma unroll
        for (int j = 0; j < 8; j++) acc[i][j] = 0ull;

    const float* a0p = A + (tg * 2) * RS;
    const float* a1p = a0p + RS;
    const float* bp  = B + ng * RS;          // rows ng, ng+8, ..., ng+56

#pragma unroll 4
    for (int k = 0; k < KK; k += 4) {
        ulonglong2 a0 = *(const ulonglong2*)(a0p + k);
        ulonglong2 a1 = *(const ulonglong2*)(a1p + k);
        ulonglong2 b[8];
#pragma unroll
        for (int j = 0; j < 8; j++)
            b[j] = *(const ulonglong2*)(bp + j * 8 * RS + k);
#pragma unroll
        for (int j = 0; j < 8; j++) {
            fma2(acc[0][j], a0.x, b[j].x);
            fma2(acc[0][j], a0.y, b[j].y);
            fma2(acc[1][j], a1.x, b[j].x);
            fma2(acc[1][j], a1.y, b[j].y);
        }
    }
#pragma unroll
    for (int i = 0; i < 2; i++)
#pragma unroll
        for (int j = 0; j < 8; j++) out[i][j] = red2(acc[i][j]);
}

__global__ __launch_bounds__(256, 1)
void win_attn_kernel(const float* __restrict__ x,
                     const float* __restrict__ ln_g, const float* __restrict__ ln_b,
                     const float* __restrict__ Win,  const float* __restrict__ bin,
                     const float* __restrict__ Wout, const float* __restrict__ bout,
                     const float* __restrict__ Wc,   const float* __restrict__ bc,
                     float* __restrict__ out) {
    extern __shared__ float sm[];
    float* XW = sm;              // [64][132] original window (residual)
    float* XN = XW + TOK * RS;   // [64][132] LN output, later attn o
    float* Qb = XN + TOK * RS;   // [64][132] q, later y = xw + attn_out
    float* Kb = Qb + TOK * RS;   // [64][132]
    float* Vb = Kb + TOK * RS;   // [64][132]
    float* WT = Vb + TOK * RS;   // [64][132] weight tile
    float* SC = WT + TOK * RS;   // [64][68]  scores (per head)

    const int tid = threadIdx.x;
    const int wid = blockIdx.x;
    const int bb  = wid >> 12;
    const int rr  = wid & 4095;
    const int vd0 = (rr >> 8) * 4;
    const int vh0 = ((rr >> 4) & 15) * 4;
    const int vw0 = (rr & 15) * 4;
    const float* xb = x + (size_t)bb * ((size_t)CCH * VOLS);
    const size_t vox0 = (size_t)vd0 * 4096 + (size_t)vh0 * 64 + vw0;

    // ---- gather window into XW ----
    for (int e = tid; e < TOK * CCH / 4; e += 256) {
        int c = e >> 4, tq = e & 15;
        int dz = tq >> 2, dy = tq & 3;
        float4 v = *(const float4*)(xb + (size_t)c * VOLS + vox0 + dz * 4096 + dy * 64);
        float* dst = XW + (dz * 16 + dy * 4) * RS + c;
        dst[0] = v.x; dst[RS] = v.y; dst[2 * RS] = v.z; dst[3 * RS] = v.w;
    }
    __syncthreads();

    // ---- LayerNorm over C=128 (4 threads per token) ----
    {
        int t = tid >> 2, sub = tid & 3;
        const float* row = XW + t * RS;
        float s = 0.f, ss = 0.f;
#pragma unroll 8
        for (int c = sub * 32; c < sub * 32 + 32; c++) { float v = row[c]; s += v; ss += v * v; }
        s  += __shfl_xor_sync(0xffffffffu, s, 1);  s  += __shfl_xor_sync(0xffffffffu, s, 2);
        ss += __shfl_xor_sync(0xffffffffu, ss, 1); ss += __shfl_xor_sync(0xffffffffu, ss, 2);
        float mu = s * (1.f / 128.f);
        float var = ss * (1.f / 128.f) - mu * mu;
        float rstd = rsqrtf(var + 1e-5f);
        float* nrow = XN + t * RS;
#pragma unroll 8
        for (int c = sub * 32; c < sub * 32 + 32; c++)
            nrow[c] = (row[c] - mu) * rstd * ln_g[c] + ln_b[c];
    }
    __syncthreads();

    const int tg = tid >> 3, ng = tid & 7;   // rows {tg*2,tg*2+1}, cols {ng+8j}

    // ---- QKV projection ----
    for (int nt = 0; nt < 6; nt++) {
        __syncthreads();
        for (int e = tid; e < 64 * 32; e += 256) {
            int o = e >> 5, k4 = e & 31;
            float4 w = *((const float4*)(Win + (size_t)(nt * 64 + o) * 128) + k4);
            *(float4*)(WT + o * RS + k4 * 4) = w;
        }
        __syncthreads();
        float accf[2][8];
        gemm28<128>(XN, WT, tg, ng, accf);
        float* dst = (nt < 2) ? Qb : (nt < 4) ? Kb : Vb;
        int cb = (nt & 1) * 64;
#pragma unroll
        for (int j = 0; j < 8; j++) {
            int oc = ng + 8 * j;
            int cl = cb + oc;
            float bias = bin[nt * 64 + oc];
            dst[(tg * 2 + 0) * RS + cl] = accf[0][j] + bias;
            dst[(tg * 2 + 1) * RS + cl] = accf[1][j] + bias;
        }
    }

    // ---- attention per head (hd=32), o written into XN ----
    const float sc_norm = 0.17677669529663687f; // 1/sqrt(32)
    for (int hh = 0; hh < 4; hh++) {
        __syncthreads();
        // scores = q_h @ k_h^T * sc_norm
        {
            float accf[2][8];
            gemm28<32>(Qb + hh * 32, Kb + hh * 32, tg, ng, accf);
#pragma unroll
            for (int i = 0; i < 2; i++)
#pragma unroll
                for (int j = 0; j < 8; j++)
                    SC[(tg * 2 + i) * SCS + ng + 8 * j] = accf[i][j] * sc_norm;
        }
        __syncthreads();
        // softmax over keys, 4 threads per row
        {
            int rrow = tid >> 2, sub = tid & 3;
            float* row = SC + rrow * SCS + sub * 16;
            float m = row[0];
#pragma unroll
            for (int c = 1; c < 16; c++) m = fmaxf(m, row[c]);
            m = fmaxf(m, __shfl_xor_sync(0xffffffffu, m, 1));
            m = fmaxf(m, __shfl_xor_sync(0xffffffffu, m, 2));
            float s = 0.f;
#pragma unroll
            for (int c = 0; c < 16; c++) { float e = __expf(row[c] - m); row[c] = e; s += e; }
            s += __shfl_xor_sync(0xffffffffu, s, 1);
            s += __shfl_xor_sync(0xffffffffu, s, 2);
            float inv = 1.f / s;
#pragma unroll
            for (int c = 0; c < 16; c++) row[c] *= inv;
        }
        __syncthreads();
        // o_h = attn @ v_h : thread rows {tg*2,tg*2+1}, cols hh*32 + ng*4..+3
        {
            u64t acc[2][2] = {{0ull, 0ull}, {0ull, 0ull}};
            const float* s0 = SC + (tg * 2) * SCS;
            const float* s1 = s0 + SCS;
            const float* vp = Vb + hh * 32 + ng * 4;
#pragma unroll 8
            for (int k = 0; k < 64; k++) {
                float a0 = s0[k], a1 = s1[k];
                ulonglong2 bv = *(const ulonglong2*)(vp + k * RS);
                u64t ap0 = pk2(a0, a0), ap1 = pk2(a1, a1);
                fma2(acc[0][0], ap0, bv.x); fma2(acc[0][1], ap0, bv.y);
                fma2(acc[1][0], ap1, bv.x); fma2(acc[1][1], ap1, bv.y);
            }
#pragma unroll
            for (int i = 0; i < 2; i++) {
                float* dst = XN + (tg * 2 + i) * RS + hh * 32 + ng * 4;
                float lo, hi;
                unpk(acc[i][0], lo, hi); dst[0] = lo; dst[1] = hi;
                unpk(acc[i][1], lo, hi); dst[2] = lo; dst[3] = hi;
            }
        }
    }

    // ---- out_proj: y = xw + o @ Wout^T + bout  (into Qb) ----
    for (int nt = 0; nt < 2; nt++) {
        __syncthreads();
        for (int e = tid; e < 64 * 32; e += 256) {
            int o = e >> 5, k4 = e & 31;
            float4 w = *((const float4*)(Wout + (size_t)(nt * 64 + o) * 128) + k4);
            *(float4*)(WT + o * RS + k4 * 4) = w;
        }
        __syncthreads();
        float accf[2][8];
        gemm28<128>(XN, WT, tg, ng, accf);
#pragma unroll
        for (int j = 0; j < 8; j++) {
            int cc = nt * 64 + ng + 8 * j;
            float bias = bout[cc];
#pragma unroll
            for (int i = 0; i < 2; i++) {
                int t = tg * 2 + i;
                Qb[t * RS + cc] = XW[t * RS + cc] + accf[i][j] + bias;
            }
        }
    }

    // ---- 1x1x1 conv + residual, scatter to global ----
    float* outp = out + (size_t)bb * ((size_t)CCH * VOLS);
    const int t0 = tg * 2;
    const int dz = t0 >> 4, dy = (t0 >> 2) & 3, dx = t0 & 3;
    for (int nt = 0; nt < 2; nt++) {
        __syncthreads();
        for (int e = tid; e < 64 * 32; e += 256) {
            int o = e >> 5, k4 = e & 31;
            float4 w = *((const float4*)(Wc + (size_t)(nt * 64 + o) * 128) + k4);
            *(float4*)(WT + o * RS + k4 * 4) = w;
        }
        __syncthreads();
        float accf[2][8];
        gemm28<128>(Qb, WT, tg, ng, accf);
#pragma unroll
        for (int j = 0; j < 8; j++) {
            int cc = nt * 64 + ng + 8 * j;
            float bias = bc[cc];
            float2 o2;
            o2.x = accf[0][j] + bias + XW[(t0 + 0) * RS + cc];
            o2.y = accf[1][j] + bias + XW[(t0 + 1) * RS + cc];
            *(float2*)(outp + (size_t)cc * VOLS + vox0 + dz * 4096 + dy * 64 + dx) = o2;
        }
    }
}

static const int SMEM_BYTES = (6 * TOK * RS + TOK * SCS) * 4; // 220160 B

extern "C" void kernel_launch(void* const* d_in, const int* in_sizes, int n_in,
                              void* d_out, int out_size) {
    const float* x    = (const float*)d_in[0];
    const float* ln_g = (const float*)d_in[1];
    const float* ln_b = (const float*)d_in[2];
    const float* Win  = (const float*)d_in[3];
    const float* bin  = (const float*)d_in[4];
    const float* Wout = (const float*)d_in[5];
    const float* bout = (const float*)d_in[6];
    const float* Wc   = (const float*)d_in[7];
    const float* bc   = (const float*)d_in[8];
    float* out = (float*)d_out;

    cudaFuncSetAttribute(win_attn_kernel,
                         cudaFuncAttributeMaxDynamicSharedMemorySize, SMEM_BYTES);
    win_attn_kernel<<<8192, 256, SMEM_BYTES>>>(x, ln_g, ln_b, Win, bin,
                                               Wout, bout, Wc, bc, out);
}

// round 4
// speedup vs baseline: 12.1698x; 2.4692x over previous
#include <cuda_runtime.h>
#include <cstdint>

// R4: all GEMMs on tensor cores (mma.sync m16n8k8 tf32), fp32 residuals exact.

#define RS    132    // row stride (floats) for [64][128] buffers; phase(r)=r mod 8
#define RSV   68     // VbT (transposed V, [128][64]) row stride
#define SCS   68     // scores row stride
#define TOK   64
#define CCH   128
#define VOLS  262144

__device__ __forceinline__ uint32_t f2tf(float f) {
    uint32_t r; asm("cvt.rna.tf32.f32 %0, %1;" : "=r"(r) : "f"(f)); return r;
}
__device__ __forceinline__ float f2tf_f(float f) { return __uint_as_float(f2tf(f)); }

__device__ __forceinline__ void mma8(float c[4], uint32_t a0, uint32_t a1,
                                     uint32_t a2, uint32_t a3,
                                     uint32_t b0, uint32_t b1) {
    asm volatile("mma.sync.aligned.m16n8k8.row.col.f32.tf32.tf32.f32 "
                 "{%0,%1,%2,%3}, {%4,%5,%6,%7}, {%8,%9}, {%0,%1,%2,%3};"
                 : "+f"(c[0]), "+f"(c[1]), "+f"(c[2]), "+f"(c[3])
                 : "r"(a0), "r"(a1), "r"(a2), "r"(a3), "r"(b0), "r"(b1));
}

// Warp computes rows [r0, r0+16) x cols [c0, c0+NT*8) of A * B^T.
// A: [rows][ras] k-contiguous; B: [cols][rbs] k-contiguous. All tf32-rounded.
// C[j][0]=D[r0+g][c0+8j+2t] C[j][1]=+1col C[j][2]=D[r0+g+8][..2t] C[j][3]=+1col
template<int KK, int NT>
__device__ __forceinline__ void mma_gemm(const float* __restrict__ A, int ras,
                                         const float* __restrict__ B, int rbs,
                                         int r0, int c0, int g, int t,
                                         float C[NT][4]) {
#pragma unroll
    for (int j = 0; j < NT; j++)
#pragma unroll
        for (int i = 0; i < 4; i++) C[j][i] = 0.f;
    const float* ap0 = A + (r0 + g) * ras;
    const float* ap1 = A + (r0 + g + 8) * ras;
#pragma unroll
    for (int k0 = 0; k0 < KK; k0 += 8) {
        uint32_t a0 = __float_as_uint(ap0[k0 + t]);
        uint32_t a1 = __float_as_uint(ap1[k0 + t]);
        uint32_t a2 = __float_as_uint(ap0[k0 + t + 4]);
        uint32_t a3 = __float_as_uint(ap1[k0 + t + 4]);
#pragma unroll
        for (int j = 0; j < NT; j++) {
            const float* bp = B + (c0 + j * 8 + g) * rbs;
            uint32_t b0 = __float_as_uint(bp[k0 + t]);
            uint32_t b1 = __float_as_uint(bp[k0 + t + 4]);
            mma8(C[j], a0, a1, a2, a3, b0, b1);
        }
    }
}

__global__ __launch_bounds__(256, 1)
void win_attn_kernel(const float* __restrict__ x,
                     const float* __restrict__ ln_g, const float* __restrict__ ln_b,
                     const float* __restrict__ Win,  const float* __restrict__ bin,
                     const float* __restrict__ Wout, const float* __restrict__ bout,
                     const float* __restrict__ Wc,   const float* __restrict__ bc,
                     float* __restrict__ out) {
    extern __shared__ float sm[];
    float* XW  = sm;                // [64][132] original window, exact fp32
    float* XN  = XW  + TOK * RS;    // [64][132] LN(tf32) -> attn o(tf32) -> conv out(fp32)
    float* Qb  = XN  + TOK * RS;    // [64][132] q(tf32) -> y(tf32)
    float* Kb  = Qb  + TOK * RS;    // [64][132] k(tf32)
    float* WT  = Kb  + TOK * RS;    // [64][132] weight tile (tf32)
    float* VbT = WT  + TOK * RS;    // [128][68] V transposed (tf32)
    float* SC  = VbT + CCH * RSV;   // [64][68]  scores / probs

    const int tid  = threadIdx.x;
    const int warp = tid >> 5;
    const int lane = tid & 31;
    const int g = lane >> 2, t = lane & 3;
    const int r0  = (warp & 3) * 16;       // warp m-tile
    const int cn0 = (warp >> 2) * 32;      // warp n-base (64-wide passes)

    const int wid = blockIdx.x;
    const int bb  = wid >> 12;
    const int rr  = wid & 4095;
    const int vd0 = (rr >> 8) * 4;
    const int vh0 = ((rr >> 4) & 15) * 4;
    const int vw0 = (rr & 15) * 4;
    const float* xb = x + (size_t)bb * ((size_t)CCH * VOLS);
    const size_t vox0 = (size_t)vd0 * 4096 + (size_t)vh0 * 64 + vw0;

    const int c0l = tid & 31, tq0 = tid >> 5;   // gather/writer mapping

    // ---- gather window into XW (lanes span 32 channels: conflict-free STS) ----
#pragma unroll
    for (int i = 0; i < 8; i++) {
        int c  = c0l + 32 * (i & 3);
        int tq = tq0 + 8 * (i >> 2);
        int dz = tq >> 2, dy = tq & 3;
        float4 v = *(const float4*)(xb + (size_t)c * VOLS + vox0 + dz * 4096 + dy * 64);
        float* dst = XW + (tq * 4) * RS + c;
        dst[0] = v.x; dst[RS] = v.y; dst[2 * RS] = v.z; dst[3 * RS] = v.w;
    }
    __syncthreads();

    // ---- LayerNorm (4 threads/token, stride-4 interleaved cols: conflict-free) ----
    {
        int tt = tid >> 2, sub = tid & 3;
        const float* row = XW + tt * RS;
        float s = 0.f, ss = 0.f;
#pragma unroll
        for (int i = 0; i < 32; i++) { float v = row[sub + 4 * i]; s += v; ss += v * v; }
        s  += __shfl_xor_sync(0xffffffffu, s, 1);  s  += __shfl_xor_sync(0xffffffffu, s, 2);
        ss += __shfl_xor_sync(0xffffffffu, ss, 1); ss += __shfl_xor_sync(0xffffffffu, ss, 2);
        float mu = s * (1.f / 128.f);
        float var = ss * (1.f / 128.f) - mu * mu;
        float rstd = rsqrtf(var + 1e-5f);
        float* nrow = XN + tt * RS;
#pragma unroll
        for (int i = 0; i < 32; i++) {
            int c = sub + 4 * i;
            nrow[c] = f2tf_f((row[c] - mu) * rstd * ln_g[c] + ln_b[c]);
        }
    }

    // ---- QKV projection (6 passes of 64 out-channels) ----
    for (int nt = 0; nt < 6; nt++) {
        __syncthreads();
        for (int e = tid; e < 64 * 32; e += 256) {
            int o = e >> 5, k4 = e & 31;
            float4 w = *((const float4*)(Win + (size_t)(nt * 64 + o) * 128) + k4);
            float* d = WT + o * RS + k4 * 4;
            d[0] = f2tf_f(w.x); d[1] = f2tf_f(w.y); d[2] = f2tf_f(w.z); d[3] = f2tf_f(w.w);
        }
        __syncthreads();
        float C[4][4];
        mma_gemm<128, 4>(XN, RS, WT, RS, r0, cn0, g, t, C);
        if (nt < 4) {
            float* dst = (nt < 2) ? Qb : Kb;
            int cb = (nt & 1) * 64;
#pragma unroll
            for (int j = 0; j < 4; j++) {
                int oc = cn0 + j * 8 + 2 * t;
                float2 b2 = *(const float2*)(bin + nt * 64 + oc);
                float2 v0 = { f2tf_f(C[j][0] + b2.x), f2tf_f(C[j][1] + b2.y) };
                float2 v1 = { f2tf_f(C[j][2] + b2.x), f2tf_f(C[j][3] + b2.y) };
                *(float2*)(dst + (r0 + g)     * RS + cb + oc) = v0;
                *(float2*)(dst + (r0 + g + 8) * RS + cb + oc) = v1;
            }
        } else {
            int cb = (nt & 1) * 64;
#pragma unroll
            for (int j = 0; j < 4; j++) {
                int oc = cn0 + j * 8 + 2 * t;
                float2 b2 = *(const float2*)(bin + nt * 64 + oc);
                int cc = cb + oc;
                VbT[(cc    ) * RSV + r0 + g]     = f2tf_f(C[j][0] + b2.x);
                VbT[(cc + 1) * RSV + r0 + g]     = f2tf_f(C[j][1] + b2.y);
                VbT[(cc    ) * RSV + r0 + g + 8] = f2tf_f(C[j][2] + b2.x);
                VbT[(cc + 1) * RSV + r0 + g + 8] = f2tf_f(C[j][3] + b2.y);
            }
        }
    }

    // ---- attention per head ----
    const float sc_norm = 0.17677669529663687f; // 1/sqrt(32)
    const int cn0_av = (warp >> 2) * 16;
    for (int hh = 0; hh < 4; hh++) {
        __syncthreads();   // SC free, Qb/Kb/VbT ready
        {
            float C[4][4];
            mma_gemm<32, 4>(Qb + hh * 32, RS, Kb + hh * 32, RS, r0, cn0, g, t, C);
#pragma unroll
            for (int j = 0; j < 4; j++) {
                int oc = cn0 + j * 8 + 2 * t;
                float2 v0 = { C[j][0] * sc_norm, C[j][1] * sc_norm };
                float2 v1 = { C[j][2] * sc_norm, C[j][3] * sc_norm };
                *(float2*)(SC + (r0 + g)     * SCS + oc) = v0;
                *(float2*)(SC + (r0 + g + 8) * SCS + oc) = v1;
            }
        }
        __syncthreads();
        // softmax over keys (4 threads/row, stride-4 cols: conflict-free)
        {
            int rrow = tid >> 2, sub = tid & 3;
            float* row = SC + rrow * SCS;
            float m = row[sub];
#pragma unroll
            for (int i = 1; i < 16; i++) m = fmaxf(m, row[sub + 4 * i]);
            m = fmaxf(m, __shfl_xor_sync(0xffffffffu, m, 1));
            m = fmaxf(m, __shfl_xor_sync(0xffffffffu, m, 2));
            float s = 0.f;
#pragma unroll
            for (int i = 0; i < 16; i++) {
                float e = __expf(row[sub + 4 * i] - m);
                row[sub + 4 * i] = e; s += e;
            }
            s += __shfl_xor_sync(0xffffffffu, s, 1);
            s += __shfl_xor_sync(0xffffffffu, s, 2);
            float inv = 1.f / s;
#pragma unroll
            for (int i = 0; i < 16; i++) {
                int c = sub + 4 * i;
                row[c] = f2tf_f(row[c] * inv);
            }
        }
        __syncthreads();
        // o_h = P @ V_h : warp tile 16 x 16 (NT=2), B = VbT rows hh*32..
        {
            float C2[2][4];
            mma_gemm<64, 2>(SC, SCS, VbT + (hh * 32) * RSV, RSV, r0, cn0_av, g, t, C2);
#pragma unroll
            for (int j = 0; j < 2; j++) {
                int oc = hh * 32 + cn0_av + j * 8 + 2 * t;
                float2 v0 = { f2tf_f(C2[j][0]), f2tf_f(C2[j][1]) };
                float2 v1 = { f2tf_f(C2[j][2]), f2tf_f(C2[j][3]) };
                *(float2*)(XN + (r0 + g)     * RS + oc) = v0;
                *(float2*)(XN + (r0 + g + 8) * RS + oc) = v1;
            }
        }
    }

    // ---- out_proj: y = xw + o @ Wout^T + bout (tf32, into Qb) ----
    for (int nt = 0; nt < 2; nt++) {
        __syncthreads();
        for (int e = tid; e < 64 * 32; e += 256) {
            int o = e >> 5, k4 = e & 31;
            float4 w = *((const float4*)(Wout + (size_t)(nt * 64 + o) * 128) + k4);
            float* d = WT + o * RS + k4 * 4;
            d[0] = f2tf_f(w.x); d[1] = f2tf_f(w.y); d[2] = f2tf_f(w.z); d[3] = f2tf_f(w.w);
        }
        __syncthreads();
        float C[4][4];
        mma_gemm<128, 4>(XN, RS, WT, RS, r0, cn0, g, t, C);
#pragma unroll
        for (int j = 0; j < 4; j++) {
            int cl = nt * 64 + cn0 + j * 8 + 2 * t;
            float2 b2 = *(const float2*)(bout + cl);
            float2 xw0 = *(const float2*)(XW + (r0 + g)     * RS + cl);
            float2 xw1 = *(const float2*)(XW + (r0 + g + 8) * RS + cl);
            float2 v0 = { f2tf_f(C[j][0] + b2.x + xw0.x), f2tf_f(C[j][1] + b2.y + xw0.y) };
            float2 v1 = { f2tf_f(C[j][2] + b2.x + xw1.x), f2tf_f(C[j][3] + b2.y + xw1.y) };
            *(float2*)(Qb + (r0 + g)     * RS + cl) = v0;
            *(float2*)(Qb + (r0 + g + 8) * RS + cl) = v1;
        }
    }

    // ---- 1x1x1 conv + residual: stage fp32 result into XN ----
    for (int nt = 0; nt < 2; nt++) {
        __syncthreads();
        for (int e = tid; e < 64 * 32; e += 256) {
            int o = e >> 5, k4 = e & 31;
            float4 w = *((const float4*)(Wc + (size_t)(nt * 64 + o) * 128) + k4);
            float* d = WT + o * RS + k4 * 4;
            d[0] = f2tf_f(w.x); d[1] = f2tf_f(w.y); d[2] = f2tf_f(w.z); d[3] = f2tf_f(w.w);
        }
        __syncthreads();
        float C[4][4];
        mma_gemm<128, 4>(Qb, RS, WT, RS, r0, cn0, g, t, C);
#pragma unroll
        for (int j = 0; j < 4; j++) {
            int cl = nt * 64 + cn0 + j * 8 + 2 * t;
            float2 b2 = *(const float2*)(bc + cl);
            float2 xw0 = *(const float2*)(XW + (r0 + g)     * RS + cl);
            float2 xw1 = *(const float2*)(XW + (r0 + g + 8) * RS + cl);
            float2 v0 = { C[j][0] + b2.x + xw0.x, C[j][1] + b2.y + xw0.y };
            float2 v1 = { C[j][2] + b2.x + xw1.x, C[j][3] + b2.y + xw1.y };
            *(float2*)(XN + (r0 + g)     * RS + cl) = v0;
            *(float2*)(XN + (r0 + g + 8) * RS + cl) = v1;
        }
    }
    __syncthreads();

    // ---- coalesced writer: XN -> out ----
    float* outp = out + (size_t)bb * ((size_t)CCH * VOLS);
#pragma unroll
    for (int i = 0; i < 8; i++) {
        int c  = c0l + 32 * (i & 3);
        int tq = tq0 + 8 * (i >> 2);
        int dz = tq >> 2, dy = tq & 3;
        const float* src = XN + (tq * 4) * RS + c;
        float4 v = { src[0], src[RS], src[2 * RS], src[3 * RS] };
        *(float4*)(outp + (size_t)c * VOLS + vox0 + dz * 4096 + dy * 64) = v;
    }
}

static const int SMEM_BYTES = (5 * TOK * RS + CCH * RSV + TOK * SCS) * 4; // 221184 B

extern "C" void kernel_launch(void* const* d_in, const int* in_sizes, int n_in,
                              void* d_out, int out_size) {
    const float* x    = (const float*)d_in[0];
    const float* ln_g = (const float*)d_in[1];
    const float* ln_b = (const float*)d_in[2];
    const float* Win  = (const float*)d_in[3];
    const float* bin  = (const float*)d_in[4];
    const float* Wout = (const float*)d_in[5];
    const float* bout = (const float*)d_in[6];
    const float* Wc   = (const float*)d_in[7];
    const float* bc   = (const float*)d_in[8];
    float* out = (float*)d_out;

    cudaFuncSetAttribute(win_attn_kernel,
                         cudaFuncAttributeMaxDynamicSharedMemorySize, SMEM_BYTES);
    win_attn_kernel<<<8192, 256, SMEM_BYTES>>>(x, ln_g, ln_b, Win, bin,
                                               Wout, bout, Wc, bc, out);
}

// round 5
// speedup vs baseline: 21.1049x; 1.7342x over previous
#include <cuda_runtime.h>
#include <cuda_bf16.h>
#include <cstdint>

// R5: bf16 mma.m16n8k16 datapath, 112KB smem -> 2 CTAs/SM. fp32 residual exact.

#define RSH  136   // halves stride for [64][128] bf16 buffers (17 16B-units, odd)
#define RSV  72    // VbT [128][64] halves stride (9 units, odd)
#define SCS  72    // scores [64][64] halves stride
#define OSTS 133   // fp32 conv-staging stride (odd -> conflict-free scalar access)
#define TOK  64
#define CCH  128
#define VOLS 262144

__device__ __forceinline__ uint32_t pkbf(float lo, float hi) {
    uint32_t r; asm("cvt.rn.bf16x2.f32 %0, %1, %2;" : "=r"(r) : "f"(hi), "f"(lo));
    return r;
}
__device__ __forceinline__ float2 upbf(uint32_t v) {
    __nv_bfloat162 h; *(uint32_t*)&h = v;
    return __bfloat1622float2(h);
}
__device__ __forceinline__ void mma16(float c[4], uint32_t a0, uint32_t a1,
                                      uint32_t a2, uint32_t a3,
                                      uint32_t b0, uint32_t b1) {
    asm volatile("mma.sync.aligned.m16n8k16.row.col.f32.bf16.bf16.f32 "
                 "{%0,%1,%2,%3}, {%4,%5,%6,%7}, {%8,%9}, {%0,%1,%2,%3};"
                 : "+f"(c[0]), "+f"(c[1]), "+f"(c[2]), "+f"(c[3])
                 : "r"(a0), "r"(a1), "r"(a2), "r"(a3), "r"(b0), "r"(b1));
}

// Warp computes rows [r0,r0+16) x cols [c0,c0+NT*8) of A(bf16) * B(bf16)^T.
// A: [rows][ras] k-contiguous halves; B: [cols][rbs] k-contiguous halves.
// C[j][0]=D[r0+g][c0+8j+2t] C[j][1]=+1col  C[j][2]/C[j][3]: row +8.
template<int KK, int NT>
__device__ __forceinline__ void mma_gemm(const __nv_bfloat16* __restrict__ A, int ras,
                                         const __nv_bfloat16* __restrict__ B, int rbs,
                                         int r0, int c0, int g, int t,
                                         float C[NT][4]) {
#pragma unroll
    for (int j = 0; j < NT; j++)
#pragma unroll
        for (int i = 0; i < 4; i++) C[j][i] = 0.f;
    const __nv_bfloat16* ap0 = A + (r0 + g) * ras + 2 * t;
    const __nv_bfloat16* ap1 = A + (r0 + g + 8) * ras + 2 * t;
#pragma unroll
    for (int k0 = 0; k0 < KK; k0 += 16) {
        uint32_t a0 = *(const uint32_t*)(ap0 + k0);
        uint32_t a1 = *(const uint32_t*)(ap1 + k0);
        uint32_t a2 = *(const uint32_t*)(ap0 + k0 + 8);
        uint32_t a3 = *(const uint32_t*)(ap1 + k0 + 8);
#pragma unroll
        for (int j = 0; j < NT; j++) {
            const __nv_bfloat16* bp = B + (c0 + j * 8 + g) * rbs + 2 * t;
            uint32_t b0 = *(const uint32_t*)(bp + k0);
            uint32_t b1 = *(const uint32_t*)(bp + k0 + 8);
            mma16(C[j], a0, a1, a2, a3, b0, b1);
        }
    }
}

__global__ __launch_bounds__(256, 2)
void win_attn_kernel(const float* __restrict__ x,
                     const float* __restrict__ ln_g, const float* __restrict__ ln_b,
                     const float* __restrict__ Win,  const float* __restrict__ bin,
                     const float* __restrict__ Wout, const float* __restrict__ bout,
                     const float* __restrict__ Wc,   const float* __restrict__ bc,
                     float* __restrict__ out) {
    extern __shared__ char smbase[];
    __nv_bfloat16* XW  = (__nv_bfloat16*)smbase;   // [64][136] x (bf16) for y-add
    __nv_bfloat16* XN  = XW  + TOK * RSH;          // [64][136] LN out -> attn o
    __nv_bfloat16* Qb  = XN  + TOK * RSH;          // [64][136] q -> y
    __nv_bfloat16* Kb  = Qb  + TOK * RSH;          // [64][136] k
    __nv_bfloat16* WT  = Kb  + TOK * RSH;          // [64][136] weight tile
    __nv_bfloat16* VbT = WT  + TOK * RSH;          // [128][72] V transposed
    __nv_bfloat16* SC  = VbT + CCH * RSV;          // [64][72]  scores/probs
    float* OST = (float*)smbase;                   // [64][133] fp32, overlaps XW+XN

    const int tid  = threadIdx.x;
    const int warp = tid >> 5;
    const int lane = tid & 31;
    const int g = lane >> 2, t = lane & 3;
    const int r0  = (warp & 3) * 16;
    const int cn0 = (warp >> 2) * 32;

    const int wid = blockIdx.x;
    const int bb  = wid >> 12;
    const int rr  = wid & 4095;
    const int vd0 = (rr >> 8) * 4;
    const int vh0 = ((rr >> 4) & 15) * 4;
    const int vw0 = (rr & 15) * 4;
    const float* xb = x + (size_t)bb * ((size_t)CCH * VOLS);
    const size_t vox0 = (size_t)vd0 * 4096 + (size_t)vh0 * 64 + vw0;

    const int c0l = tid & 31, tq0 = tid >> 5;

    // ---- gather window into XW (bf16) ----
#pragma unroll
    for (int i = 0; i < 8; i++) {
        int c  = c0l + 32 * (i & 3);
        int tq = tq0 + 8 * (i >> 2);
        int dz = tq >> 2, dy = tq & 3;
        float4 v = *(const float4*)(xb + (size_t)c * VOLS + vox0 + dz * 4096 + dy * 64);
        __nv_bfloat16* dst = XW + (tq * 4) * RSH + c;
        dst[0]       = __float2bfloat16(v.x);
        dst[RSH]     = __float2bfloat16(v.y);
        dst[2 * RSH] = __float2bfloat16(v.z);
        dst[3 * RSH] = __float2bfloat16(v.w);
    }
    __syncthreads();

    // ---- LayerNorm (4 threads/token, paired cols {2sub+8i}) ----
    {
        int tt = tid >> 2, sub = tid & 3;
        const __nv_bfloat16* row = XW + tt * RSH;
        float s = 0.f, ss = 0.f;
        float2 vals[16];
#pragma unroll
        for (int i = 0; i < 16; i++) {
            float2 v = upbf(*(const uint32_t*)(row + 2 * sub + 8 * i));
            vals[i] = v;
            s += v.x + v.y; ss += v.x * v.x + v.y * v.y;
        }
        s  += __shfl_xor_sync(0xffffffffu, s, 1);  s  += __shfl_xor_sync(0xffffffffu, s, 2);
        ss += __shfl_xor_sync(0xffffffffu, ss, 1); ss += __shfl_xor_sync(0xffffffffu, ss, 2);
        float mu = s * (1.f / 128.f);
        float var = ss * (1.f / 128.f) - mu * mu;
        float rstd = rsqrtf(var + 1e-5f);
        __nv_bfloat16* nrow = XN + tt * RSH;
#pragma unroll
        for (int i = 0; i < 16; i++) {
            int c = 2 * sub + 8 * i;
            float2 gl = *(const float2*)(ln_g + c);
            float2 bl = *(const float2*)(ln_b + c);
            *(uint32_t*)(nrow + c) = pkbf((vals[i].x - mu) * rstd * gl.x + bl.x,
                                          (vals[i].y - mu) * rstd * gl.y + bl.y);
        }
    }

    // ---- QKV projection (6 passes of 64 out-channels) ----
    for (int nt = 0; nt < 6; nt++) {
        __syncthreads();
        for (int e = tid; e < 64 * 32; e += 256) {
            int o = e >> 5, k4 = e & 31;
            float4 w = *((const float4*)(Win + (size_t)(nt * 64 + o) * 128) + k4);
            uint2 p = { pkbf(w.x, w.y), pkbf(w.z, w.w) };
            *(uint2*)(WT + o * RSH + k4 * 4) = p;
        }
        __syncthreads();
        float C[4][4];
        mma_gemm<128, 4>(XN, RSH, WT, RSH, r0, cn0, g, t, C);
        if (nt < 4) {
            __nv_bfloat16* dst = (nt < 2) ? Qb : Kb;
            int cb = (nt & 1) * 64;
#pragma unroll
            for (int j = 0; j < 4; j++) {
                int oc = cn0 + j * 8 + 2 * t;
                float2 b2 = *(const float2*)(bin + nt * 64 + oc);
                *(uint32_t*)(dst + (r0 + g)     * RSH + cb + oc) =
                    pkbf(C[j][0] + b2.x, C[j][1] + b2.y);
                *(uint32_t*)(dst + (r0 + g + 8) * RSH + cb + oc) =
                    pkbf(C[j][2] + b2.x, C[j][3] + b2.y);
            }
        } else {
            int cb = (nt & 1) * 64;
#pragma unroll
            for (int j = 0; j < 4; j++) {
                int oc = cn0 + j * 8 + 2 * t;
                float2 b2 = *(const float2*)(bin + nt * 64 + oc);
                int cc = cb + oc;
                VbT[(cc    ) * RSV + r0 + g]     = __float2bfloat16(C[j][0] + b2.x);
                VbT[(cc + 1) * RSV + r0 + g]     = __float2bfloat16(C[j][1] + b2.y);
                VbT[(cc    ) * RSV + r0 + g + 8] = __float2bfloat16(C[j][2] + b2.x);
                VbT[(cc + 1) * RSV + r0 + g + 8] = __float2bfloat16(C[j][3] + b2.y);
            }
        }
    }

    // ---- attention per head ----
    const float sc_norm = 0.17677669529663687f; // 1/sqrt(32)
    const int cn0_av = (warp >> 2) * 16;
    for (int hh = 0; hh < 4; hh++) {
        __syncthreads();
        {
            float C[4][4];
            mma_gemm<32, 4>(Qb + hh * 32, RSH, Kb + hh * 32, RSH, r0, cn0, g, t, C);
#pragma unroll
            for (int j = 0; j < 4; j++) {
                int oc = cn0 + j * 8 + 2 * t;
                *(uint32_t*)(SC + (r0 + g)     * SCS + oc) =
                    pkbf(C[j][0] * sc_norm, C[j][1] * sc_norm);
                *(uint32_t*)(SC + (r0 + g + 8) * SCS + oc) =
                    pkbf(C[j][2] * sc_norm, C[j][3] * sc_norm);
            }
        }
        __syncthreads();
        // softmax (4 threads/row, pair cols {2sub+8i})
        {
            int rrow = tid >> 2, sub = tid & 3;
            __nv_bfloat16* row = SC + rrow * SCS + 2 * sub;
            float2 v[8];
            float m = -1e30f;
#pragma unroll
            for (int i = 0; i < 8; i++) {
                v[i] = upbf(*(const uint32_t*)(row + 8 * i));
                m = fmaxf(m, fmaxf(v[i].x, v[i].y));
            }
            m = fmaxf(m, __shfl_xor_sync(0xffffffffu, m, 1));
            m = fmaxf(m, __shfl_xor_sync(0xffffffffu, m, 2));
            float s = 0.f;
#pragma unroll
            for (int i = 0; i < 8; i++) {
                v[i].x = __expf(v[i].x - m);
                v[i].y = __expf(v[i].y - m);
                s += v[i].x + v[i].y;
            }
            s += __shfl_xor_sync(0xffffffffu, s, 1);
            s += __shfl_xor_sync(0xffffffffu, s, 2);
            float inv = 1.f / s;
#pragma unroll
            for (int i = 0; i < 8; i++)
                *(uint32_t*)(row + 8 * i) = pkbf(v[i].x * inv, v[i].y * inv);
        }
        __syncthreads();
        // o_h = P @ V_h : warp tile 16x16 (NT=2)
        {
            float C2[2][4];
            mma_gemm<64, 2>(SC, SCS, VbT + (hh * 32) * RSV, RSV, r0, cn0_av, g, t, C2);
#pragma unroll
            for (int j = 0; j < 2; j++) {
                int oc = hh * 32 + cn0_av + j * 8 + 2 * t;
                *(uint32_t*)(XN + (r0 + g)     * RSH + oc) = pkbf(C2[j][0], C2[j][1]);
                *(uint32_t*)(XN + (r0 + g + 8) * RSH + oc) = pkbf(C2[j][2], C2[j][3]);
            }
        }
    }

    // ---- out_proj: y = xw + o @ Wout^T + bout  (bf16, into Qb) ----
    for (int nt = 0; nt < 2; nt++) {
        __syncthreads();
        for (int e = tid; e < 64 * 32; e += 256) {
            int o = e >> 5, k4 = e & 31;
            float4 w = *((const float4*)(Wout + (size_t)(nt * 64 + o) * 128) + k4);
            uint2 p = { pkbf(w.x, w.y), pkbf(w.z, w.w) };
            *(uint2*)(WT + o * RSH + k4 * 4) = p;
        }
        __syncthreads();
        float C[4][4];
        mma_gemm<128, 4>(XN, RSH, WT, RSH, r0, cn0, g, t, C);
#pragma unroll
        for (int j = 0; j < 4; j++) {
            int cl = nt * 64 + cn0 + j * 8 + 2 * t;
            float2 b2 = *(const float2*)(bout + cl);
            float2 xw0 = upbf(*(const uint32_t*)(XW + (r0 + g)     * RSH + cl));
            float2 xw1 = upbf(*(const uint32_t*)(XW + (r0 + g + 8) * RSH + cl));
            *(uint32_t*)(Qb + (r0 + g)     * RSH + cl) =
                pkbf(C[j][0] + b2.x + xw0.x, C[j][1] + b2.y + xw0.y);
            *(uint32_t*)(Qb + (r0 + g + 8) * RSH + cl) =
                pkbf(C[j][2] + b2.x + xw1.x, C[j][3] + b2.y + xw1.y);
        }
    }

    // ---- 1x1x1 conv: stage fp32 (conv + bias) into OST (overlaps XW/XN) ----
    for (int nt = 0; nt < 2; nt++) {
        __syncthreads();
        for (int e = tid; e < 64 * 32; e += 256) {
            int o = e >> 5, k4 = e & 31;
            float4 w = *((const float4*)(Wc + (size_t)(nt * 64 + o) * 128) + k4);
            uint2 p = { pkbf(w.x, w.y), pkbf(w.z, w.w) };
            *(uint2*)(WT + o * RSH + k4 * 4) = p;
        }
        __syncthreads();
        float C[4][4];
        mma_gemm<128, 4>(Qb, RSH, WT, RSH, r0, cn0, g, t, C);
#pragma unroll
        for (int j = 0; j < 4; j++) {
            int cl = nt * 64 + cn0 + j * 8 + 2 * t;
            float2 b2 = *(const float2*)(bc + cl);
            float* o0 = OST + (r0 + g)     * OSTS + cl;
            float* o1 = OST + (r0 + g + 8) * OSTS + cl;
            o0[0] = C[j][0] + b2.x; o0[1] = C[j][1] + b2.y;
            o1[0] = C[j][2] + b2.x; o1[1] = C[j][3] + b2.y;
        }
    }
    __syncthreads();

    // ---- epilogue: out = OST + x (exact fp32 residual), coalesced ----
    float* outp = out + (size_t)bb * ((size_t)CCH * VOLS);
#pragma unroll
    for (int i = 0; i < 8; i++) {
        int c  = c0l + 32 * (i & 3);
        int tq = tq0 + 8 * (i >> 2);
        int dz = tq >> 2, dy = tq & 3;
        size_t gaddr = (size_t)c * VOLS + vox0 + dz * 4096 + dy * 64;
        float4 xv = *(const float4*)(xb + gaddr);
        const float* src = OST + (tq * 4) * OSTS + c;
        float4 v = { src[0] + xv.x, src[OSTS] + xv.y,
                     src[2 * OSTS] + xv.z, src[3 * OSTS] + xv.w };
        *(float4*)(outp + gaddr) = v;
    }
}

static const int SMEM_BYTES = (5 * TOK * RSH + CCH * RSV + TOK * SCS) * 2; // 114688 B

extern "C" void kernel_launch(void* const* d_in, const int* in_sizes, int n_in,
                              void* d_out, int out_size) {
    const float* x    = (const float*)d_in[0];
    const float* ln_g = (const float*)d_in[1];
    const float* ln_b = (const float*)d_in[2];
    const float* Win  = (const float*)d_in[3];
    const float* bin  = (const float*)d_in[4];
    const float* Wout = (const float*)d_in[5];
    const float* bout = (const float*)d_in[6];
    const float* Wc   = (const float*)d_in[7];
    const float* bc   = (const float*)d_in[8];
    float* out = (float*)d_out;

    cudaFuncSetAttribute(win_attn_kernel,
                         cudaFuncAttributeMaxDynamicSharedMemorySize, SMEM_BYTES);
    win_attn_kernel<<<8192, 256, SMEM_BYTES>>>(x, ln_g, ln_b, Win, bin,
                                               Wout, bout, Wc, bc, out);
}